// round 15
// baseline (speedup 1.0000x reference)
#include <cuda_runtime.h>
#include <cuda_fp16.h>
#include <cstdint>
#include <math.h>

// Problem constants
#define Bb 64
#define Ll 128
#define Ee 512
#define Hh 512
#define Vv 32000
#define Tt 127
#define MR (Tt*Bb)      // 8128 rows (t,b)
#define MP 8192         // padded rows for 128-tile GEMMs

// Output layout: [loss(1)] [attns T*B*L] [h_fin B*H] [logits B*V]
#define OFF_ATTN 1L
#define OFF_HF   (1L + (long)Tt*Bb*Ll)
#define OFF_LOG  (OFF_HF + (long)Bb*Hh)

// ---------------- scratch (static device globals; no allocs) ----------------
// NOTE: reference these ONLY from device code (host-side use yields the host
// shadow symbol; ATS makes it silently read host zeros — R3/4/6/7 root cause).
__device__ float g_xseq[(long)MP*Ee];
__device__ float g_decin[(long)MP*Ee];
__device__ float g_gi[(long)MP*3*Hh];
__device__ float g_attnx[(long)MP*Ll];
__device__ float g_hseq[(long)MP*Hh];
__device__ float g_h0[Bb*Hh];
__device__ float g_whhP[3*Hh*Hh];    // permuted W_hh: block jt rows contiguous
__device__ float g_wattnT[Hh*Ll];
__device__ float g_lse_m[256L*MP];   // [chunk][m] chunk-major
__device__ float g_lse_s[256L*MP];
__device__ float g_ztgt[MP];
__device__ float g_ce[MR];

// ---------------- helpers ----------------------------------------------------
__device__ __forceinline__ unsigned f2h2(float x, float y) {
    __half2 h = __floats2half2_rn(x, y);   // low = x, high = y
    return *(unsigned*)&h;
}

// fp16 HMMA m16n8k16, fp32 accumulate (A row-major, B col-major)
__device__ __forceinline__ void mma_f16(float d[4], const unsigned a[4],
                                        const unsigned b[2], const float c[4]) {
    asm volatile(
        "mma.sync.aligned.m16n8k16.row.col.f32.f16.f16.f32 "
        "{%0,%1,%2,%3},{%4,%5,%6,%7},{%8,%9},{%10,%11,%12,%13};"
        : "=f"(d[0]), "=f"(d[1]), "=f"(d[2]), "=f"(d[3])
        : "r"(a[0]), "r"(a[1]), "r"(a[2]), "r"(a[3]),
          "r"(b[0]), "r"(b[1]),
          "f"(c[0]), "f"(c[1]), "f"(c[2]), "f"(c[3]));
}

// packed fp32x2 FMA (Blackwell family ISA; each lane is an exact fp32 FMA)
__device__ __forceinline__ unsigned long long pk2(float x, float y) {
    unsigned long long r;
    asm("mov.b64 %0, {%1, %2};" : "=l"(r) : "f"(x), "f"(y));
    return r;
}
__device__ __forceinline__ void upk2(unsigned long long v, float& x, float& y) {
    asm("mov.b64 {%0, %1}, %2;" : "=f"(x), "=f"(y) : "l"(v));
}
__device__ __forceinline__ void ffma2(unsigned long long& d,
                                      unsigned long long a, unsigned long long b) {
    asm("fma.rn.f32x2 %0, %1, %2, %0;" : "+l"(d) : "l"(a), "l"(b));
}

// ---------------- init ---------------------------------------------------------
__global__ void k_init(const float* __restrict__ W_attn) {
    int idx = blockIdx.x * blockDim.x + threadIdx.x;  // 65536 threads
    if (idx < Bb*Hh) g_h0[idx] = 0.f;
    if (idx < (MP-MR)*Hh) g_hseq[(long)MR*Hh + idx] = 0.f;
    if (idx < (MP-MR)*Ee) {
        g_xseq[(long)MR*Ee + idx] = 0.f;
        g_decin[(long)MR*Ee + idx] = 0.f;
    }
    if (idx < Hh*Ll) {
        int k = idx >> 7, l = idx & 127;
        g_wattnT[idx] = W_attn[l*(2*Hh) + Hh + k];
    }
}

// permute W_hh: block jt (j-tile of 8) gets 24 contiguous rows =
// [gate0 j0..j7, gate1 j0..j7, gate2 j0..j7]
__global__ void k_prep(const float* __restrict__ W_hh) {
    int r = blockIdx.x;               // 0..1535
    int jt = r / 24, rem = r % 24;
    int gate = rem >> 3, jj = rem & 7;
    int src = gate*Hh + jt*8 + jj;
    float4* d = (float4*)(g_whhP + (long)r*Hh);
    const float4* s = (const float4*)(W_hh + (long)src*Hh);
    d[threadIdx.x] = s[threadIdx.x];  // 128 threads x float4 = 512 floats
}

// ---------------- embedding gather ------------------------------------------
__global__ void k_embed(const int* __restrict__ dec, const float* __restrict__ emb) {
    int m = blockIdx.x;            // 0..MR-1
    int t = m / Bb, b = m % Bb;
    int tok_x = dec[b*Ll + t];
    int tp = (t > 0) ? (t - 1) : 0;
    int tok_d = dec[b*Ll + tp];
    const float4* ex = (const float4*)(emb + (long)tok_x * Ee);
    const float4* ed = (const float4*)(emb + (long)tok_d * Ee);
    float4* ox = (float4*)(g_xseq + (long)m * Ee);
    float4* od = (float4*)(g_decin + (long)m * Ee);
    int i = threadIdx.x;           // 128 threads
    ox[i] = ex[i];
    od[i] = ed[i];
}

// ---------------- big fp32 GEMM body (128x128 tile, K=512, f32x2 FMAs) -------
__device__ __forceinline__ void big_body(
    const float* __restrict__ A, int lda,
    const float* __restrict__ Bw, int ldb,
    const float* __restrict__ bias,
    float* __restrict__ C, long ldc, int rowlim)
{
    __shared__ float As[16][132];
    __shared__ float Bs[16][132];
    int tid = threadIdx.x;
    int tx = tid & 15, ty = tid >> 4;
    int m0 = blockIdx.y * 128, n0 = blockIdx.x * 128;
    int lr = tid >> 2;
    int lc = (tid & 3) << 2;
    unsigned long long acc2[8][4];
    #pragma unroll
    for (int i = 0; i < 8; i++)
        #pragma unroll
        for (int j = 0; j < 4; j++) acc2[i][j] = 0ULL;

    for (int kk = 0; kk < 512; kk += 16) {
        #pragma unroll
        for (int r = 0; r < 2; r++) {
            int row = lr + r*64;
            float4 av = *(const float4*)(A + (long)(m0 + row)*lda + kk + lc);
            float4 bv = *(const float4*)(Bw + (long)(n0 + row)*ldb + kk + lc);
            As[lc+0][row]=av.x; As[lc+1][row]=av.y; As[lc+2][row]=av.z; As[lc+3][row]=av.w;
            Bs[lc+0][row]=bv.x; Bs[lc+1][row]=bv.y; Bs[lc+2][row]=bv.z; Bs[lc+3][row]=bv.w;
        }
        __syncthreads();
        #pragma unroll
        for (int k = 0; k < 16; k++) {
            float4 a0 = *(const float4*)&As[k][ty*8];
            float4 a1 = *(const float4*)&As[k][ty*8 + 4];
            float4 b0 = *(const float4*)&Bs[k][tx*8];
            float4 b1 = *(const float4*)&Bs[k][tx*8 + 4];
            float aa[8] = {a0.x,a0.y,a0.z,a0.w,a1.x,a1.y,a1.z,a1.w};
            unsigned long long bb2[4] = { pk2(b0.x,b0.y), pk2(b0.z,b0.w),
                                          pk2(b1.x,b1.y), pk2(b1.z,b1.w) };
            #pragma unroll
            for (int i = 0; i < 8; i++) {
                unsigned long long aa2 = pk2(aa[i], aa[i]);
                #pragma unroll
                for (int j = 0; j < 4; j++)
                    ffma2(acc2[i][j], aa2, bb2[j]);
            }
        }
        __syncthreads();
    }
    float bj[8];
    #pragma unroll
    for (int j = 0; j < 8; j++) bj[j] = bias[n0 + tx*8 + j];
    #pragma unroll
    for (int i = 0; i < 8; i++) {
        int m = m0 + ty*8 + i;
        if (m < rowlim) {
            #pragma unroll
            for (int j = 0; j < 4; j++) {
                float v0, v1;
                upk2(acc2[i][j], v0, v1);
                C[(long)m*ldc + n0 + tx*8 + 2*j]     = v0 + bj[2*j];
                C[(long)m*ldc + n0 + tx*8 + 2*j + 1] = v1 + bj[2*j + 1];
            }
        }
    }
}

__global__ void __launch_bounds__(256)
k_gi(const float* __restrict__ W_ih, const float* __restrict__ b_ih) {
    big_body(g_xseq, Ee, W_ih, Ee, b_ih, g_gi, 3*Hh, MP);
}
__global__ void __launch_bounds__(256)
k_attnx(const float* __restrict__ W_attn, const float* __restrict__ b_attn) {
    big_body(g_decin, Ee, W_attn, 2*Hh, b_attn, g_attnx, Ll, MP);
}

// ---------------- fp32 SGEMM 64x64 (f32x2) for logits -------------------------
__device__ __forceinline__ void sgemm_body(
    const float* __restrict__ A, int lda,
    const float* __restrict__ Bm, int ldb,
    const float* __restrict__ bias,
    float* __restrict__ C, long ldc, int K)
{
    __shared__ float As[16][68];
    __shared__ float Bs[16][68];
    int tid = threadIdx.x;
    int tx = tid & 15, ty = tid >> 4;
    int m0 = blockIdx.y * 64, n0 = blockIdx.x * 64;
    int lr = tid >> 2;
    int lc = (tid & 3) << 2;
    unsigned long long acc2[4][2] = {};
    const float* Ap = A + (long)(m0 + lr) * lda + lc;
    const float* Bp = Bm + (long)(n0 + lr) * ldb + lc;
    for (int kk = 0; kk < K; kk += 16) {
        float4 av = *(const float4*)(Ap + kk);
        float4 bv = *(const float4*)(Bp + kk);
        As[lc+0][lr]=av.x; As[lc+1][lr]=av.y; As[lc+2][lr]=av.z; As[lc+3][lr]=av.w;
        Bs[lc+0][lr]=bv.x; Bs[lc+1][lr]=bv.y; Bs[lc+2][lr]=bv.z; Bs[lc+3][lr]=bv.w;
        __syncthreads();
        #pragma unroll
        for (int k = 0; k < 16; k++) {
            float4 a4 = *(const float4*)&As[k][ty*4];
            float4 b4 = *(const float4*)&Bs[k][tx*4];
            float aa[4] = {a4.x, a4.y, a4.z, a4.w};
            unsigned long long bb2[2] = { pk2(b4.x,b4.y), pk2(b4.z,b4.w) };
            #pragma unroll
            for (int i = 0; i < 4; i++) {
                unsigned long long aa2 = pk2(aa[i], aa[i]);
                ffma2(acc2[i][0], aa2, bb2[0]);
                ffma2(acc2[i][1], aa2, bb2[1]);
            }
        }
        __syncthreads();
    }
    #pragma unroll
    for (int i = 0; i < 4; i++) {
        int m = m0 + ty*4 + i;
        #pragma unroll
        for (int j = 0; j < 2; j++) {
            float v0, v1;
            upk2(acc2[i][j], v0, v1);
            int n = n0 + tx*4 + 2*j;
            C[(long)m * ldc + n]     = v0 + bias[n];
            C[(long)m * ldc + n + 1] = v1 + bias[n + 1];
        }
    }
}
__global__ void k_logits(const float* __restrict__ W_out, const float* __restrict__ b_out,
                         float* __restrict__ out) {
    sgemm_body(g_hseq + (long)(Tt-1)*Bb*Hh, Hh, W_out, Hh, b_out,
               out + OFF_LOG, Vv, Hh);
}

// ---------------- fused per-step kernel: ONE launch per timestep --------------
// 96 blocks x 256 threads.
//   blocks 0..63 : j-tile of 8. GEMM C[64 b][24 = 3 gates x 8 j] = h @ whhP^T
//                  (K=512) into smem, then GRU gates -> h(t) in-block.
//   blocks 64..95: attention for 2 batch rows each (R9-validated code).
__global__ void __launch_bounds__(256)
k_step(const float* __restrict__ b_hh, int t, float* __restrict__ out)
{
    __shared__ float As[32][65];     // [k][b]
    __shared__ float Bs[32][26];     // [k][24n pad26]
    __shared__ float Cg[64][25];     // gh tile [b][24n pad25]
    __shared__ float hs2[2][512];
    __shared__ float redm[2][4];
    __shared__ float reds[2][4];
    int blk = blockIdx.x, tid = threadIdx.x;
    const float* hp = (t == 0) ? g_h0 : (g_hseq + (long)(t-1)*Bb*Hh);

    if (blk < 64) {
        // ---- GEMM: C[64 b][24 n], n = gate*8 + jj, j = blk*8 + jj ----
        const float* Bp = g_whhP + (long)blk*24*Hh;
        int ty = tid >> 2;           // b = ty (0..63)
        int tx = tid & 3;            // n group = tx*6 (0..18)
        unsigned long long acc2[3] = {};
        for (int kk = 0; kk < Hh; kk += 32) {
            // stage A: 64 b x 32 k (512 float4, 2 per thread), transposed
            #pragma unroll
            for (int u = 0; u < 2; u++) {
                int f = tid*2 + u;                 // 0..511
                int row = f >> 3, kc = (f & 7) << 2;
                float4 v = *(const float4*)(hp + (long)row*Hh + kk + kc);
                As[kc+0][row] = v.x; As[kc+1][row] = v.y;
                As[kc+2][row] = v.z; As[kc+3][row] = v.w;
            }
            // stage B: 24 n x 32 k (192 float4), transposed
            if (tid < 192) {
                int row = tid >> 3, kc = (tid & 7) << 2;
                float4 v = *(const float4*)(Bp + (long)row*Hh + kk + kc);
                Bs[kc+0][row] = v.x; Bs[kc+1][row] = v.y;
                Bs[kc+2][row] = v.z; Bs[kc+3][row] = v.w;
            }
            __syncthreads();
            #pragma unroll 8
            for (int k = 0; k < 32; k++) {
                float a = As[k][ty];
                unsigned long long aa2 = pk2(a, a);
                const float2* br = (const float2*)&Bs[k][tx*6];
                float2 b0 = br[0], b1 = br[1], b2 = br[2];
                ffma2(acc2[0], aa2, pk2(b0.x, b0.y));
                ffma2(acc2[1], aa2, pk2(b1.x, b1.y));
                ffma2(acc2[2], aa2, pk2(b2.x, b2.y));
            }
            __syncthreads();
        }
        #pragma unroll
        for (int j = 0; j < 3; j++) {
            float v0, v1;
            upk2(acc2[j], v0, v1);
            Cg[ty][tx*6 + 2*j]     = v0;
            Cg[ty][tx*6 + 2*j + 1] = v1;
        }
        __syncthreads();
        // ---- gates: 64 b x 8 jj = 512 outputs, 2 per thread ----
        #pragma unroll
        for (int u = 0; u < 2; u++) {
            int idx = tid*2 + u;
            int b = idx >> 3, jj = idx & 7;
            int j = blk*8 + jj;
            float hr = Cg[b][jj]      + b_hh[j];
            float hz = Cg[b][8 + jj]  + b_hh[Hh + j];
            float hn = Cg[b][16 + jj] + b_hh[2*Hh + j];
            long gib = (long)(t*Bb + b) * (3*Hh);
            float r = 1.f / (1.f + expf(-(g_gi[gib + j] + hr)));
            float z = 1.f / (1.f + expf(-(g_gi[gib + Hh + j] + hz)));
            float n = tanhf(g_gi[gib + 2*Hh + j] + r * hn);
            float hprev = hp[b*Hh + j];
            g_hseq[(long)(t*Bb + b) * Hh + j] = (1.f - z) * n + z * hprev;
        }
    } else {
        // ---- attention: 2 batch rows per block (R9-validated) ----
        int half = tid >> 7;            // 0 or 1
        int l = tid & 127;              // logit index
        int wl = (tid >> 5) & 3;        // warp within half
        int b = (blk - 64) * 2 + half;
        #pragma unroll
        for (int u = 0; u < 4; u++)
            hs2[half][l + u*128] = hp[b*Hh + l + u*128];
        __syncthreads();
        float logit = g_attnx[(long)(t*Bb + b)*Ll + l];
        const float* wt = g_wattnT + l;
        const float* hh = hs2[half];
        #pragma unroll 8
        for (int k = 0; k < 512; k++)
            logit += hh[k] * wt[(long)k*Ll];
        float mx = logit;
        #pragma unroll
        for (int off = 16; off > 0; off >>= 1)
            mx = fmaxf(mx, __shfl_xor_sync(0xffffffffu, mx, off));
        if ((tid & 31) == 0) redm[half][wl] = mx;
        __syncthreads();
        mx = fmaxf(fmaxf(redm[half][0], redm[half][1]),
                   fmaxf(redm[half][2], redm[half][3]));
        float e = expf(logit - mx);
        float se = e;
        #pragma unroll
        for (int off = 16; off > 0; off >>= 1)
            se += __shfl_xor_sync(0xffffffffu, se, off);
        if ((tid & 31) == 0) reds[half][wl] = se;
        __syncthreads();
        se = reds[half][0] + reds[half][1] + reds[half][2] + reds[half][3];
        out[OFF_ATTN + ((long)t*Bb + b)*Ll + l] = e / se;
    }
}

// ---------------- copy final hidden state ------------------------------------
__global__ void k_hfin(float* __restrict__ out) {
    int b = blockIdx.x, j = threadIdx.x;
    out[OFF_HF + (long)b*Hh + j] = g_hseq[(long)((Tt-1)*Bb + b)*Hh + j];
}

// ---------------- vocab fp16 HMMA GEMM + fused online logsumexp (R11) --------
__global__ void __launch_bounds__(256)
k_vocab(const float* __restrict__ Bw, const float* __restrict__ bias,
        const int* __restrict__ dec)
{
    __shared__ unsigned As[2][128][12];   // half2: 8 per row (16 k), pad 12
    __shared__ unsigned Bs[2][128][12];
    __shared__ float red_m[128][4];
    __shared__ float red_s[128][4];

    int tid = threadIdx.x;
    int warp = tid >> 5, lane = tid & 31;
    int wm = warp & 1, wn = warp >> 1;
    int m0 = blockIdx.y * 128, n0 = blockIdx.x * 128;
    int qr = lane >> 2, qc = lane & 3;
    int lrow = tid >> 1, lcol = (tid & 1) * 4;   // 4 half2 per thread

    float acc[4][4][4] = {};
    const float* Ap = g_hseq + (long)(m0 + lrow) * Hh + lcol*2;
    const float* Bp = Bw + (long)(n0 + lrow) * Hh + lcol*2;

    float4 ra0 = *(const float4*)(Ap);
    float4 ra1 = *(const float4*)(Ap + 4);
    float4 rb0 = *(const float4*)(Bp);
    float4 rb1 = *(const float4*)(Bp + 4);

    #define STAGE(buf)                                                 \
        As[buf][lrow][lcol+0] = f2h2(ra0.x, ra0.y);                    \
        As[buf][lrow][lcol+1] = f2h2(ra0.z, ra0.w);                    \
        As[buf][lrow][lcol+2] = f2h2(ra1.x, ra1.y);                    \
        As[buf][lrow][lcol+3] = f2h2(ra1.z, ra1.w);                    \
        Bs[buf][lrow][lcol+0] = f2h2(rb0.x, rb0.y);                    \
        Bs[buf][lrow][lcol+1] = f2h2(rb0.z, rb0.w);                    \
        Bs[buf][lrow][lcol+2] = f2h2(rb1.x, rb1.y);                    \
        Bs[buf][lrow][lcol+3] = f2h2(rb1.z, rb1.w);

    STAGE(0)

    for (int i = 0; i < 32; i++) {         // 32 iterations x 16 k = 512
        __syncthreads();
        if (i < 31) {
            int kk = (i + 1) * 16;
            ra0 = *(const float4*)(Ap + kk);
            ra1 = *(const float4*)(Ap + kk + 4);
            rb0 = *(const float4*)(Bp + kk);
            rb1 = *(const float4*)(Bp + kk + 4);
        }
        int buf = i & 1;
        unsigned af[4][4], bf[4][2];
        #pragma unroll
        for (int mi = 0; mi < 4; mi++) {
            int r = wm*64 + mi*16 + qr;
            af[mi][0] = As[buf][r  ][qc];
            af[mi][1] = As[buf][r+8][qc];
            af[mi][2] = As[buf][r  ][qc+4];
            af[mi][3] = As[buf][r+8][qc+4];
        }
        #pragma unroll
        for (int ni = 0; ni < 4; ni++) {
            int c = wn*32 + ni*8 + qr;
            bf[ni][0] = Bs[buf][c][qc];
            bf[ni][1] = Bs[buf][c][qc+4];
        }
        #pragma unroll
        for (int mi = 0; mi < 4; mi++)
            #pragma unroll
            for (int ni = 0; ni < 4; ni++)
                mma_f16(acc[mi][ni], af[mi], bf[ni], acc[mi][ni]);
        if (i < 31) { STAGE(buf ^ 1) }
    }
    #undef STAGE

    // bias
    #pragma unroll
    for (int ni = 0; ni < 4; ni++) {
        int n = n0 + wn*32 + ni*8 + 2*qc;
        float bv0 = bias[n], bv1 = bias[n+1];
        #pragma unroll
        for (int mi = 0; mi < 4; mi++) {
            acc[mi][ni][0] += bv0; acc[mi][ni][1] += bv1;
            acc[mi][ni][2] += bv0; acc[mi][ni][3] += bv1;
        }
    }

    // per-row chunk max + sumexp
    #pragma unroll
    for (int mi = 0; mi < 4; mi++) {
        #pragma unroll
        for (int h = 0; h < 2; h++) {
            float mx = -1e30f;
            #pragma unroll
            for (int ni = 0; ni < 4; ni++) {
                mx = fmaxf(mx, acc[mi][ni][h*2]);
                mx = fmaxf(mx, acc[mi][ni][h*2+1]);
            }
            mx = fmaxf(mx, __shfl_xor_sync(0xffffffffu, mx, 1));
            mx = fmaxf(mx, __shfl_xor_sync(0xffffffffu, mx, 2));
            float se = 0.f;
            #pragma unroll
            for (int ni = 0; ni < 4; ni++) {
                se += expf(acc[mi][ni][h*2]   - mx);
                se += expf(acc[mi][ni][h*2+1] - mx);
            }
            se += __shfl_xor_sync(0xffffffffu, se, 1);
            se += __shfl_xor_sync(0xffffffffu, se, 2);
            if (qc == 0) {
                int lr = wm*64 + mi*16 + h*8 + qr;
                red_m[lr][wn] = mx;
                red_s[lr][wn] = se;
            }
        }
    }

    // target gather
    #pragma unroll
    for (int mi = 0; mi < 4; mi++) {
        #pragma unroll
        for (int h = 0; h < 2; h++) {
            int mg = m0 + wm*64 + mi*16 + h*8 + qr;
            if (mg < MR) {
                int t = mg >> 6, b = mg & 63;
                int tgt = dec[b*Ll + t];
                #pragma unroll
                for (int ni = 0; ni < 4; ni++) {
                    int n = n0 + wn*32 + ni*8 + 2*qc;
                    if (n == tgt)   g_ztgt[mg] = acc[mi][ni][h*2];
                    if (n+1 == tgt) g_ztgt[mg] = acc[mi][ni][h*2+1];
                }
            }
        }
    }
    __syncthreads();

    if (tid < 128) {
        int row = tid;
        float M = red_m[row][0];
        M = fmaxf(M, red_m[row][1]);
        M = fmaxf(M, red_m[row][2]);
        M = fmaxf(M, red_m[row][3]);
        float S = 0.f;
        #pragma unroll
        for (int w = 0; w < 4; w++) S += red_s[row][w] * expf(red_m[row][w] - M);
        int mg = m0 + row;
        if (mg < MR) {
            g_lse_m[(long)blockIdx.x*MP + mg] = M;   // chunk-major (coalesced)
            g_lse_s[(long)blockIdx.x*MP + mg] = S;
        }
    }
}

// ---------------- combine chunk (m,s) -> per-row CE --------------------------
__global__ void k_rowce() {
    int m = blockIdx.x * 128 + threadIdx.x;
    if (m >= MR) return;
    float M = -1e30f, S = 0.f;
    #pragma unroll 5
    for (int c = 0; c < 250; c++) {
        float mc = g_lse_m[(long)c*MP + m];
        float sc = g_lse_s[(long)c*MP + m];
        float Mn = fmaxf(M, mc);
        S = S * expf(M - Mn) + sc * expf(mc - Mn);
        M = Mn;
    }
    g_ce[m] = (M + logf(S)) - g_ztgt[m];
}

__global__ void k_loss(float* __restrict__ out) {
    __shared__ float red[256];
    float s = 0.f;
    for (int m = threadIdx.x; m < MR; m += 256) s += g_ce[m];
    red[threadIdx.x] = s;
    __syncthreads();
    for (int off = 128; off > 0; off >>= 1) {
        if (threadIdx.x < off) red[threadIdx.x] += red[threadIdx.x + off];
        __syncthreads();
    }
    if (threadIdx.x == 0) out[0] = red[0] / (float)Bb;
}

// ---------------- launcher ----------------------------------------------------
extern "C" void kernel_launch(void* const* d_in, const int* in_sizes, int n_in,
                              void* d_out, int out_size) {
    (void)in_sizes; (void)n_in; (void)out_size;
    const int*   dec    = (const int*)d_in[0];
    const float* emb    = (const float*)d_in[3];
    const float* W_attn = (const float*)d_in[4];
    const float* b_attn = (const float*)d_in[5];
    const float* W_ih   = (const float*)d_in[6];
    const float* W_hh   = (const float*)d_in[7];
    const float* b_ih   = (const float*)d_in[8];
    const float* b_hh   = (const float*)d_in[9];
    const float* W_out  = (const float*)d_in[10];
    const float* b_out  = (const float*)d_in[11];
    float* out = (float*)d_out;

    k_init<<<64, 1024>>>(W_attn);
    k_prep<<<1536, 128>>>(W_hh);
    k_embed<<<MR, 128>>>(dec, emb);
    k_gi<<<dim3(12, 64), 256>>>(W_ih, b_ih);
    k_attnx<<<dim3(1, 64), 256>>>(W_attn, b_attn);
    for (int t = 0; t < Tt; t++) {
        k_step<<<96, 256>>>(b_hh, t, out);     // gh+gates ∥ attention, 1 launch
    }
    k_hfin<<<64, 512>>>(out);
    k_vocab<<<dim3(250, 64), 256>>>(W_out, b_out, dec);
    k_logits<<<dim3(500, 1), 256>>>(W_out, b_out, out);
    k_rowce<<<64, 128>>>();
    k_loss<<<1, 256>>>(out);
}

// round 16
// speedup vs baseline: 1.9439x; 1.9439x over previous
#include <cuda_runtime.h>
#include <cuda_fp16.h>
#include <cstdint>
#include <math.h>

// Problem constants
#define Bb 64
#define Ll 128
#define Ee 512
#define Hh 512
#define Vv 32000
#define Tt 127
#define MR (Tt*Bb)      // 8128 rows (t,b)
#define MP 8192         // padded rows for 128-tile GEMMs

// Output layout: [loss(1)] [attns T*B*L] [h_fin B*H] [logits B*V]
#define OFF_ATTN 1L
#define OFF_HF   (1L + (long)Tt*Bb*Ll)
#define OFF_LOG  (OFF_HF + (long)Bb*Hh)

// ---------------- scratch (static device globals; no allocs) ----------------
// NOTE: reference these ONLY from device code (host-side use yields the host
// shadow symbol; ATS makes it silently read host zeros — R3/4/6/7 root cause).
__device__ float g_xseq[(long)MP*Ee];
__device__ float g_decin[(long)MP*Ee];
__device__ float g_gi[(long)MP*3*Hh];
__device__ float g_attnx[(long)MP*Ll];
__device__ float g_hseq[(long)MP*Hh];
__device__ float g_h0[Bb*Hh];
__device__ float g_wattnT[Hh*Ll];
__device__ float g_ghpart[4*Bb*3*Hh];
__device__ float g_lse_m[256L*MP];   // [chunk][m] chunk-major
__device__ float g_lse_s[256L*MP];
__device__ float g_ztgt[MP];
__device__ float g_ce[MR];
__device__ __align__(16) __half g_hh[(long)MP*Hh];   // h in fp16
__device__ __align__(16) __half g_wo[(long)Vv*Hh];   // W_out in fp16

// ---------------- helpers ----------------------------------------------------
__device__ __forceinline__ unsigned f2h2(float x, float y) {
    __half2 h = __floats2half2_rn(x, y);   // low = x, high = y
    return *(unsigned*)&h;
}

// fp16 HMMA m16n8k16, fp32 accumulate (A row-major, B col-major)
__device__ __forceinline__ void mma_f16(float d[4], const unsigned a[4],
                                        const unsigned b[2], const float c[4]) {
    asm volatile(
        "mma.sync.aligned.m16n8k16.row.col.f32.f16.f16.f32 "
        "{%0,%1,%2,%3},{%4,%5,%6,%7},{%8,%9},{%10,%11,%12,%13};"
        : "=f"(d[0]), "=f"(d[1]), "=f"(d[2]), "=f"(d[3])
        : "r"(a[0]), "r"(a[1]), "r"(a[2]), "r"(a[3]),
          "r"(b[0]), "r"(b[1]),
          "f"(c[0]), "f"(c[1]), "f"(c[2]), "f"(c[3]));
}

// packed fp32x2 FMA (Blackwell family ISA; each lane is an exact fp32 FMA)
__device__ __forceinline__ unsigned long long pk2(float x, float y) {
    unsigned long long r;
    asm("mov.b64 %0, {%1, %2};" : "=l"(r) : "f"(x), "f"(y));
    return r;
}
__device__ __forceinline__ void upk2(unsigned long long v, float& x, float& y) {
    asm("mov.b64 {%0, %1}, %2;" : "=f"(x), "=f"(y) : "l"(v));
}
__device__ __forceinline__ void ffma2(unsigned long long& d,
                                      unsigned long long a, unsigned long long b) {
    asm("fma.rn.f32x2 %0, %1, %2, %0;" : "+l"(d) : "l"(a), "l"(b));
}

// ---------------- init ---------------------------------------------------------
__global__ void k_init(const float* __restrict__ W_attn) {
    int idx = blockIdx.x * blockDim.x + threadIdx.x;  // 65536 threads
    if (idx < Bb*Hh) g_h0[idx] = 0.f;
    if (idx < (MP-MR)*Hh) g_hseq[(long)MR*Hh + idx] = 0.f;
    if (idx < (MP-MR)*Ee) {
        g_xseq[(long)MR*Ee + idx] = 0.f;
        g_decin[(long)MR*Ee + idx] = 0.f;
    }
    if (idx < Hh*Ll) {
        int k = idx >> 7, l = idx & 127;
        g_wattnT[idx] = W_attn[l*(2*Hh) + Hh + k];
    }
}

// ---------------- fp32 -> fp16 conversion kernels ----------------------------
__device__ __forceinline__ void cvt8(const float* __restrict__ s, __half* __restrict__ d) {
    float4 a = *(const float4*)s;
    float4 b = *(const float4*)(s + 4);
    uint4 o;
    o.x = f2h2(a.x, a.y); o.y = f2h2(a.z, a.w);
    o.z = f2h2(b.x, b.y); o.w = f2h2(b.z, b.w);
    *(uint4*)d = o;
}
__global__ void k_cvt_w(const float* __restrict__ W_out) {   // grid 8000 x 256
    long i = ((long)blockIdx.x * 256 + threadIdx.x) * 8;
    cvt8(W_out + i, g_wo + i);
}
__global__ void k_cvt_h() {                                   // grid 2048 x 256
    long i = ((long)blockIdx.x * 256 + threadIdx.x) * 8;
    cvt8(g_hseq + i, g_hh + i);
}

// ---------------- embedding gather ------------------------------------------
__global__ void k_embed(const int* __restrict__ dec, const float* __restrict__ emb) {
    int m = blockIdx.x;            // 0..MR-1
    int t = m / Bb, b = m % Bb;
    int tok_x = dec[b*Ll + t];
    int tp = (t > 0) ? (t - 1) : 0;
    int tok_d = dec[b*Ll + tp];
    const float4* ex = (const float4*)(emb + (long)tok_x * Ee);
    const float4* ed = (const float4*)(emb + (long)tok_d * Ee);
    float4* ox = (float4*)(g_xseq + (long)m * Ee);
    float4* od = (float4*)(g_decin + (long)m * Ee);
    int i = threadIdx.x;           // 128 threads
    ox[i] = ex[i];
    od[i] = ed[i];
}

// ---------------- big fp32 GEMM body (128x128 tile, K=512, f32x2 FMAs) -------
__device__ __forceinline__ void big_body(
    const float* __restrict__ A, int lda,
    const float* __restrict__ Bw, int ldb,
    const float* __restrict__ bias,
    float* __restrict__ C, long ldc, int rowlim)
{
    __shared__ float As[16][132];
    __shared__ float Bs[16][132];
    int tid = threadIdx.x;
    int tx = tid & 15, ty = tid >> 4;
    int m0 = blockIdx.y * 128, n0 = blockIdx.x * 128;
    int lr = tid >> 2;
    int lc = (tid & 3) << 2;
    unsigned long long acc2[8][4];
    #pragma unroll
    for (int i = 0; i < 8; i++)
        #pragma unroll
        for (int j = 0; j < 4; j++) acc2[i][j] = 0ULL;

    for (int kk = 0; kk < 512; kk += 16) {
        #pragma unroll
        for (int r = 0; r < 2; r++) {
            int row = lr + r*64;
            float4 av = *(const float4*)(A + (long)(m0 + row)*lda + kk + lc);
            float4 bv = *(const float4*)(Bw + (long)(n0 + row)*ldb + kk + lc);
            As[lc+0][row]=av.x; As[lc+1][row]=av.y; As[lc+2][row]=av.z; As[lc+3][row]=av.w;
            Bs[lc+0][row]=bv.x; Bs[lc+1][row]=bv.y; Bs[lc+2][row]=bv.z; Bs[lc+3][row]=bv.w;
        }
        __syncthreads();
        #pragma unroll
        for (int k = 0; k < 16; k++) {
            float4 a0 = *(const float4*)&As[k][ty*8];
            float4 a1 = *(const float4*)&As[k][ty*8 + 4];
            float4 b0 = *(const float4*)&Bs[k][tx*8];
            float4 b1 = *(const float4*)&Bs[k][tx*8 + 4];
            float aa[8] = {a0.x,a0.y,a0.z,a0.w,a1.x,a1.y,a1.z,a1.w};
            unsigned long long bb2[4] = { pk2(b0.x,b0.y), pk2(b0.z,b0.w),
                                          pk2(b1.x,b1.y), pk2(b1.z,b1.w) };
            #pragma unroll
            for (int i = 0; i < 8; i++) {
                unsigned long long aa2 = pk2(aa[i], aa[i]);
                #pragma unroll
                for (int j = 0; j < 4; j++)
                    ffma2(acc2[i][j], aa2, bb2[j]);
            }
        }
        __syncthreads();
    }
    float bj[8];
    #pragma unroll
    for (int j = 0; j < 8; j++) bj[j] = bias[n0 + tx*8 + j];
    #pragma unroll
    for (int i = 0; i < 8; i++) {
        int m = m0 + ty*8 + i;
        if (m < rowlim) {
            #pragma unroll
            for (int j = 0; j < 4; j++) {
                float v0, v1;
                upk2(acc2[i][j], v0, v1);
                C[(long)m*ldc + n0 + tx*8 + 2*j]     = v0 + bj[2*j];
                C[(long)m*ldc + n0 + tx*8 + 2*j + 1] = v1 + bj[2*j + 1];
            }
        }
    }
}

__global__ void __launch_bounds__(256)
k_gi(const float* __restrict__ W_ih, const float* __restrict__ b_ih) {
    big_body(g_xseq, Ee, W_ih, Ee, b_ih, g_gi, 3*Hh, MP);
}
__global__ void __launch_bounds__(256)
k_attnx(const float* __restrict__ W_attn, const float* __restrict__ b_attn) {
    big_body(g_decin, Ee, W_attn, 2*Hh, b_attn, g_attnx, Ll, MP);
}

// ---------------- fp32 SGEMM 64x64 (f32x2) for logits -------------------------
__device__ __forceinline__ void sgemm_body(
    const float* __restrict__ A, int lda,
    const float* __restrict__ Bm, int ldb,
    const float* __restrict__ bias,
    float* __restrict__ C, long ldc, int K)
{
    __shared__ float As[16][68];
    __shared__ float Bs[16][68];
    int tid = threadIdx.x;
    int tx = tid & 15, ty = tid >> 4;
    int m0 = blockIdx.y * 64, n0 = blockIdx.x * 64;
    int lr = tid >> 2;
    int lc = (tid & 3) << 2;
    unsigned long long acc2[4][2] = {};
    const float* Ap = A + (long)(m0 + lr) * lda + lc;
    const float* Bp = Bm + (long)(n0 + lr) * ldb + lc;
    for (int kk = 0; kk < K; kk += 16) {
        float4 av = *(const float4*)(Ap + kk);
        float4 bv = *(const float4*)(Bp + kk);
        As[lc+0][lr]=av.x; As[lc+1][lr]=av.y; As[lc+2][lr]=av.z; As[lc+3][lr]=av.w;
        Bs[lc+0][lr]=bv.x; Bs[lc+1][lr]=bv.y; Bs[lc+2][lr]=bv.z; Bs[lc+3][lr]=bv.w;
        __syncthreads();
        #pragma unroll
        for (int k = 0; k < 16; k++) {
            float4 a4 = *(const float4*)&As[k][ty*4];
            float4 b4 = *(const float4*)&Bs[k][tx*4];
            float aa[4] = {a4.x, a4.y, a4.z, a4.w};
            unsigned long long bb2[2] = { pk2(b4.x,b4.y), pk2(b4.z,b4.w) };
            #pragma unroll
            for (int i = 0; i < 4; i++) {
                unsigned long long aa2 = pk2(aa[i], aa[i]);
                ffma2(acc2[i][0], aa2, bb2[0]);
                ffma2(acc2[i][1], aa2, bb2[1]);
            }
        }
        __syncthreads();
    }
    #pragma unroll
    for (int i = 0; i < 4; i++) {
        int m = m0 + ty*4 + i;
        #pragma unroll
        for (int j = 0; j < 2; j++) {
            float v0, v1;
            upk2(acc2[i][j], v0, v1);
            int n = n0 + tx*4 + 2*j;
            C[(long)m * ldc + n]     = v0 + bias[n];
            C[(long)m * ldc + n + 1] = v1 + bias[n + 1];
        }
    }
}
__global__ void k_logits(const float* __restrict__ W_out, const float* __restrict__ b_out,
                         float* __restrict__ out) {
    sgemm_body(g_hseq + (long)(Tt-1)*Bb*Hh, Hh, W_out, Hh, b_out,
               out + OFF_LOG, Vv, Hh);
}

// ---------------- per-step launch 1: gh GEMM (blocks 0..95) ∥ attention ------
__global__ void __launch_bounds__(512)
k_stepA(const float* __restrict__ W_hh, int t, float* __restrict__ out)
{
    __shared__ float As[64][68];
    __shared__ float Bs[64][68];
    __shared__ float hs[Hh];
    __shared__ float part[4][Ll];
    __shared__ float r2[Ll];
    int blk = blockIdx.x, tid = threadIdx.x;
    const float* hp = (t == 0) ? g_h0 : (g_hseq + (long)(t-1)*Bb*Hh);

    if (blk < 96) {
        int bx = blk % 24;
        int bz = blk / 24;
        int n0 = bx * 64;
        int k0 = bz * 128;
        int tx = tid & 15, ty = (tid >> 4) & 15;
        unsigned long long acc2[4][2] = {};
        #pragma unroll
        for (int kk = k0; kk < k0 + 128; kk += 64) {
            int lr = tid >> 4;
            int lc = (tid & 15) << 2;
            #pragma unroll
            for (int rr = 0; rr < 2; rr++) {
                int row = lr + rr*32;
                float4 av = *(const float4*)(hp + (long)row*Hh + kk + lc);
                float4 bv = *(const float4*)(W_hh + (long)(n0 + row)*Hh + kk + lc);
                As[lc+0][row]=av.x; As[lc+1][row]=av.y; As[lc+2][row]=av.z; As[lc+3][row]=av.w;
                Bs[lc+0][row]=bv.x; Bs[lc+1][row]=bv.y; Bs[lc+2][row]=bv.z; Bs[lc+3][row]=bv.w;
            }
            __syncthreads();
            if (tid < 256) {
                #pragma unroll 8
                for (int k = 0; k < 64; k++) {
                    float4 a4 = *(const float4*)&As[k][ty*4];
                    float4 b4 = *(const float4*)&Bs[k][tx*4];
                    float aa[4] = {a4.x, a4.y, a4.z, a4.w};
                    unsigned long long bb2[2] = { pk2(b4.x,b4.y), pk2(b4.z,b4.w) };
                    #pragma unroll
                    for (int i = 0; i < 4; i++) {
                        unsigned long long aa2 = pk2(aa[i], aa[i]);
                        ffma2(acc2[i][0], aa2, bb2[0]);
                        ffma2(acc2[i][1], aa2, bb2[1]);
                    }
                }
            }
            __syncthreads();
        }
        if (tid < 256) {
            float* Cp = g_ghpart + (long)bz * Bb * (3*Hh);
            #pragma unroll
            for (int i = 0; i < 4; i++)
                #pragma unroll
                for (int j = 0; j < 2; j++) {
                    float v0, v1;
                    upk2(acc2[i][j], v0, v1);
                    Cp[(long)(ty*4 + i) * (3*Hh) + n0 + tx*4 + 2*j]     = v0;
                    Cp[(long)(ty*4 + i) * (3*Hh) + n0 + tx*4 + 2*j + 1] = v1;
                }
        }
    } else {
        // attention logits (h half) + softmax for batch b (verbatim R5)
        int b = blk - 96;
        hs[tid] = hp[b*Hh + tid];
        __syncthreads();
        int l = tid & 127, p = tid >> 7;
        float s = 0.f;
        const float* wt = g_wattnT + p*128*Ll + l;
        const float* hh = hs + p*128;
        #pragma unroll 8
        for (int k = 0; k < 128; k++) s += hh[k] * wt[k*Ll];
        part[p][l] = s;
        __syncthreads();
        float logit = -1e30f;
        if (tid < 128) {
            logit = part[0][tid] + part[1][tid] + part[2][tid] + part[3][tid]
                  + g_attnx[(long)(t*Bb + b)*Ll + tid];
            r2[tid] = logit;
        }
        __syncthreads();
        for (int off = 64; off > 0; off >>= 1) {
            if (tid < off) r2[tid] = fmaxf(r2[tid], r2[tid + off]);
            __syncthreads();
        }
        float mx = r2[0];
        __syncthreads();
        float e = (tid < 128) ? expf(logit - mx) : 0.f;
        if (tid < 128) r2[tid] = e;
        __syncthreads();
        for (int off = 64; off > 0; off >>= 1) {
            if (tid < off) r2[tid] += r2[tid + off];
            __syncthreads();
        }
        if (tid < 128) out[OFF_ATTN + ((long)t*Bb + b)*Ll + tid] = e / r2[0];
    }
}

// ---------------- per-step launch 2: GRU gates -> h(t) -----------------------
__global__ void __launch_bounds__(512)
k_gates(const float* __restrict__ b_hh, int t)
{
    const float* hp = (t == 0) ? g_h0 : (g_hseq + (long)(t-1)*Bb*Hh);
    int b = blockIdx.x, j = threadIdx.x;
    long gb = (long)b * (3*Hh);
    float hr = g_ghpart[gb + j]          + g_ghpart[98304 + gb + j]
             + g_ghpart[2*98304 + gb + j]+ g_ghpart[3*98304 + gb + j] + b_hh[j];
    float hz = g_ghpart[gb + Hh + j]          + g_ghpart[98304 + gb + Hh + j]
             + g_ghpart[2*98304 + gb + Hh + j]+ g_ghpart[3*98304 + gb + Hh + j] + b_hh[Hh + j];
    float hn = g_ghpart[gb + 2*Hh + j]          + g_ghpart[98304 + gb + 2*Hh + j]
             + g_ghpart[2*98304 + gb + 2*Hh + j]+ g_ghpart[3*98304 + gb + 2*Hh + j] + b_hh[2*Hh + j];
    long gib = (long)(t*Bb + b) * (3*Hh);
    float r = 1.f / (1.f + expf(-(g_gi[gib + j] + hr)));
    float z = 1.f / (1.f + expf(-(g_gi[gib + Hh + j] + hz)));
    float n = tanhf(g_gi[gib + 2*Hh + j] + r * hn);
    float hprev = hp[b*Hh + j];
    g_hseq[(long)(t*Bb + b) * Hh + j] = (1.f - z) * n + z * hprev;
}

// ---------------- copy final hidden state ------------------------------------
__global__ void k_hfin(float* __restrict__ out) {
    int b = blockIdx.x, j = threadIdx.x;
    out[OFF_HF + (long)b*Hh + j] = g_hseq[(long)((Tt-1)*Bb + b)*Hh + j];
}

// ---------------- vocab fp16 HMMA GEMM + fused online logsumexp --------------
// fp16 inputs pre-converted (g_hh, g_wo): halves L2 traffic vs fp32-load+cvt.
__global__ void __launch_bounds__(256)
k_vocab(const float* __restrict__ bias, const int* __restrict__ dec)
{
    __shared__ unsigned As[2][128][12];   // half2: 8 per row (16 k), pad 12
    __shared__ unsigned Bs[2][128][12];
    __shared__ float red_m[128][4];
    __shared__ float red_s[128][4];

    int tid = threadIdx.x;
    int warp = tid >> 5, lane = tid & 31;
    int wm = warp & 1, wn = warp >> 1;
    int m0 = blockIdx.y * 128, n0 = blockIdx.x * 128;
    int qr = lane >> 2, qc = lane & 3;
    int lrow = tid >> 1, lcol = (tid & 1) * 4;   // 4 half2 per thread

    float acc[4][4][4] = {};
    const __half* Ap = g_hh + (long)(m0 + lrow) * Hh + lcol*2;
    const __half* Bp = g_wo + (long)(n0 + lrow) * Hh + lcol*2;

    uint4 ra = *(const uint4*)(Ap);
    uint4 rb = *(const uint4*)(Bp);

    #define STAGE(buf)                                                 \
        As[buf][lrow][lcol+0] = ra.x; As[buf][lrow][lcol+1] = ra.y;    \
        As[buf][lrow][lcol+2] = ra.z; As[buf][lrow][lcol+3] = ra.w;    \
        Bs[buf][lrow][lcol+0] = rb.x; Bs[buf][lrow][lcol+1] = rb.y;    \
        Bs[buf][lrow][lcol+2] = rb.z; Bs[buf][lrow][lcol+3] = rb.w;

    STAGE(0)

    for (int i = 0; i < 32; i++) {         // 32 iterations x 16 k = 512
        __syncthreads();
        if (i < 31) {
            int kk = (i + 1) * 16;
            ra = *(const uint4*)(Ap + kk);
            rb = *(const uint4*)(Bp + kk);
        }
        int buf = i & 1;
        unsigned af[4][4], bf[4][2];
        #pragma unroll
        for (int mi = 0; mi < 4; mi++) {
            int r = wm*64 + mi*16 + qr;
            af[mi][0] = As[buf][r  ][qc];
            af[mi][1] = As[buf][r+8][qc];
            af[mi][2] = As[buf][r  ][qc+4];
            af[mi][3] = As[buf][r+8][qc+4];
        }
        #pragma unroll
        for (int ni = 0; ni < 4; ni++) {
            int c = wn*32 + ni*8 + qr;
            bf[ni][0] = Bs[buf][c][qc];
            bf[ni][1] = Bs[buf][c][qc+4];
        }
        #pragma unroll
        for (int mi = 0; mi < 4; mi++)
            #pragma unroll
            for (int ni = 0; ni < 4; ni++)
                mma_f16(acc[mi][ni], af[mi], bf[ni], acc[mi][ni]);
        if (i < 31) { STAGE(buf ^ 1) }
    }
    #undef STAGE

    // bias
    #pragma unroll
    for (int ni = 0; ni < 4; ni++) {
        int n = n0 + wn*32 + ni*8 + 2*qc;
        float bv0 = bias[n], bv1 = bias[n+1];
        #pragma unroll
        for (int mi = 0; mi < 4; mi++) {
            acc[mi][ni][0] += bv0; acc[mi][ni][1] += bv1;
            acc[mi][ni][2] += bv0; acc[mi][ni][3] += bv1;
        }
    }

    // per-row chunk max + sumexp
    #pragma unroll
    for (int mi = 0; mi < 4; mi++) {
        #pragma unroll
        for (int h = 0; h < 2; h++) {
            float mx = -1e30f;
            #pragma unroll
            for (int ni = 0; ni < 4; ni++) {
                mx = fmaxf(mx, acc[mi][ni][h*2]);
                mx = fmaxf(mx, acc[mi][ni][h*2+1]);
            }
            mx = fmaxf(mx, __shfl_xor_sync(0xffffffffu, mx, 1));
            mx = fmaxf(mx, __shfl_xor_sync(0xffffffffu, mx, 2));
            float se = 0.f;
            #pragma unroll
            for (int ni = 0; ni < 4; ni++) {
                se += expf(acc[mi][ni][h*2]   - mx);
                se += expf(acc[mi][ni][h*2+1] - mx);
            }
            se += __shfl_xor_sync(0xffffffffu, se, 1);
            se += __shfl_xor_sync(0xffffffffu, se, 2);
            if (qc == 0) {
                int lr = wm*64 + mi*16 + h*8 + qr;
                red_m[lr][wn] = mx;
                red_s[lr][wn] = se;
            }
        }
    }

    // target gather
    #pragma unroll
    for (int mi = 0; mi < 4; mi++) {
        #pragma unroll
        for (int h = 0; h < 2; h++) {
            int mg = m0 + wm*64 + mi*16 + h*8 + qr;
            if (mg < MR) {
                int t = mg >> 6, b = mg & 63;
                int tgt = dec[b*Ll + t];
                #pragma unroll
                for (int ni = 0; ni < 4; ni++) {
                    int n = n0 + wn*32 + ni*8 + 2*qc;
                    if (n == tgt)   g_ztgt[mg] = acc[mi][ni][h*2];
                    if (n+1 == tgt) g_ztgt[mg] = acc[mi][ni][h*2+1];
                }
            }
        }
    }
    __syncthreads();

    if (tid < 128) {
        int row = tid;
        float M = red_m[row][0];
        M = fmaxf(M, red_m[row][1]);
        M = fmaxf(M, red_m[row][2]);
        M = fmaxf(M, red_m[row][3]);
        float S = 0.f;
        #pragma unroll
        for (int w = 0; w < 4; w++) S += red_s[row][w] * expf(red_m[row][w] - M);
        int mg = m0 + row;
        if (mg < MR) {
            g_lse_m[(long)blockIdx.x*MP + mg] = M;   // chunk-major (coalesced)
            g_lse_s[(long)blockIdx.x*MP + mg] = S;
        }
    }
}

// ---------------- combine chunk (m,s) -> per-row CE --------------------------
__global__ void k_rowce() {
    int m = blockIdx.x * 128 + threadIdx.x;
    if (m >= MR) return;
    float M = -1e30f, S = 0.f;
    #pragma unroll 5
    for (int c = 0; c < 250; c++) {
        float mc = g_lse_m[(long)c*MP + m];
        float sc = g_lse_s[(long)c*MP + m];
        float Mn = fmaxf(M, mc);
        S = S * expf(M - Mn) + sc * expf(mc - Mn);
        M = Mn;
    }
    g_ce[m] = (M + logf(S)) - g_ztgt[m];
}

__global__ void k_loss(float* __restrict__ out) {
    __shared__ float red[256];
    float s = 0.f;
    for (int m = threadIdx.x; m < MR; m += 256) s += g_ce[m];
    red[threadIdx.x] = s;
    __syncthreads();
    for (int off = 128; off > 0; off >>= 1) {
        if (threadIdx.x < off) red[threadIdx.x] += red[threadIdx.x + off];
        __syncthreads();
    }
    if (threadIdx.x == 0) out[0] = red[0] / (float)Bb;
}

// ---------------- launcher ----------------------------------------------------
extern "C" void kernel_launch(void* const* d_in, const int* in_sizes, int n_in,
                              void* d_out, int out_size) {
    (void)in_sizes; (void)n_in; (void)out_size;
    const int*   dec    = (const int*)d_in[0];
    const float* emb    = (const float*)d_in[3];
    const float* W_attn = (const float*)d_in[4];
    const float* b_attn = (const float*)d_in[5];
    const float* W_ih   = (const float*)d_in[6];
    const float* W_hh   = (const float*)d_in[7];
    const float* b_ih   = (const float*)d_in[8];
    const float* b_hh   = (const float*)d_in[9];
    const float* W_out  = (const float*)d_in[10];
    const float* b_out  = (const float*)d_in[11];
    float* out = (float*)d_out;

    k_init<<<64, 1024>>>(W_attn);
    k_embed<<<MR, 128>>>(dec, emb);
    k_gi<<<dim3(12, 64), 256>>>(W_ih, b_ih);
    k_attnx<<<dim3(1, 64), 256>>>(W_attn, b_attn);
    k_cvt_w<<<8000, 256>>>(W_out);
    for (int t = 0; t < Tt; t++) {
        k_stepA<<<160, 512>>>(W_hh, t, out);   // gh GEMM ∥ attention
        k_gates<<<64, 512>>>(b_hh, t);         // gates -> h(t)
    }
    k_hfin<<<64, 512>>>(out);
    k_cvt_h<<<2048, 256>>>();
    k_vocab<<<dim3(250, 64), 256>>>(b_out, dec);
    k_logits<<<dim3(500, 1), 256>>>(W_out, b_out, out);
    k_rowce<<<64, 128>>>();
    k_loss<<<1, 256>>>(out);
}